// round 6
// baseline (speedup 1.0000x reference)
#include <cuda_runtime.h>
#include <math_constants.h>

#define NB 64
#define NA 5
#define NC 20
#define NH 38
#define NW 38
#define HW (NH*NW)            // 1444
#define MAXB 50
#define RPB 2                 // grid rows per block
#define GX (NH/RPB)           // 19
#define TPB 192
#define CELLS_ROW (NA*NW)     // 190
#define NCELL (RPB*CELLS_ROW) // 380
#define NBLK (GX*NB)          // 1216

__constant__ float c_aw[5] = {1.3221f, 3.19275f, 5.05587f, 9.47112f, 11.2364f};
__constant__ float c_ah[5] = {1.73145f, 4.00944f, 8.09892f, 4.84053f, 10.0071f};

__device__ double             g_part[GX];
__device__ unsigned long long g_ctr;     // monotone across replays, never reset

__device__ __forceinline__ float fsig(float v){
  return __fdividef(1.0f, 1.0f + __expf(-v));
}

// ---------------------------------------------------------------------------
// One fused kernel, 8 blocks/SM (reg-capped) => single wave at 75% occupancy.
// Block = (batch b, rows j0..j0+1), 192 thr, 2 cells/thread.
// ---------------------------------------------------------------------------
__global__ void __launch_bounds__(TPB, 8) region_kernel(const float* __restrict__ out,
                                                        const float* __restrict__ tgt,
                                                        float* __restrict__ res){
  const int b   = blockIdx.y;
  const int j0  = blockIdx.x * RPB;
  const int tid = threadIdx.x;

  __shared__ float4 s_A[MAXB];      // tx, ty, tw, th
  __shared__ float2 s_B[MAXB];      // tconf(iou_gt), gcls
  __shared__ float4 s_cb[MAXB];     // candidates (xlo,xhi,ylo,yhi)
  __shared__ float  s_ccg[MAXB];    // 0.375*areaG
  __shared__ int    s_akey[MAXB];
  __shared__ int    s_at[MAXB];
  __shared__ int    s_nc, s_na, s_w0all, s_islast;
  __shared__ float  s_ws[TPB/32];

  if (tid == 0){ s_nc = 0; s_na = 0; }

  // ---- tgt load + ballot prefix-AND validity ----
  float gcls=0.f, gx=0.f, gy=0.f, gw=0.f, gh=0.f, xn=1.0f;
  if (tid < MAXB){
    const float* p = tgt + b*(MAXB*5) + tid*5;
    gcls = p[0]; xn = p[1];
    gx = xn*(float)NW; gy = p[2]*(float)NH; gw = p[3]*(float)NW; gh = p[4]*(float)NH;
  }
  unsigned msk  = __ballot_sync(0xffffffffu, xn != 0.0f);
  const int lane = tid & 31;
  unsigned need = 0xffffffffu >> (31 - lane);
  int      pre  = ((msk & need) == need);
  if (tid == 0) s_w0all = (msk == 0xffffffffu);

  // ---- cell indices + prefetch (10 LDGs in flight before the barrier) ----
  const int c0 = tid;
  const int c1 = (tid + TPB < NCELL) ? (tid + TPB) : tid;  // clamp dup; masked later
  const bool has1 = (tid + TPB < NCELL);

  const int r0 = c0 / CELLS_ROW, q0 = c0 - r0*CELLS_ROW;
  const int a0 = q0 / NW,        i0 = q0 - a0*NW,  jj0 = j0 + r0;
  const int r1 = c1 / CELLS_ROW, q1 = c1 - r1*CELLS_ROW;
  const int a1 = q1 / NW,        i1 = q1 - a1*NW,  jj1 = j0 + r1;
  const int base0 = ((b*NA + a0)*25)*HW + jj0*NW + i0;
  const int base1 = ((b*NA + a1)*25)*HW + jj1*NW + i1;

  float p00 = out[base0],        p10 = out[base1];
  float p01 = out[base0 +   HW], p11 = out[base1 +   HW];
  float p02 = out[base0 + 2*HW], p12 = out[base1 + 2*HW];
  float p03 = out[base0 + 3*HW], p13 = out[base1 + 3*HW];
  float p04 = out[base0 + 4*HW], p14 = out[base1 + 4*HW];

  __syncthreads();

  // ---- Phase A: per-GT-box prep (warps 0-1) ----
  if (tid < MAXB){
    int valid = (tid < 32) ? pre : (pre & s_w0all);

    int best = 0; float bi = -1.0f, bu = 1.0f;
    #pragma unroll
    for (int a = 0; a < NA; ++a){
      float inter = fminf(gw, c_aw[a]) * fminf(gh, c_ah[a]);
      float uni   = gw*gh + c_aw[a]*c_ah[a] - inter;
      if (inter*bu > bi*uni){ bi = inter; bu = uni; best = a; }
    }

    int gi = min(max((int)gx, 0), NW-1);
    int gj = min(max((int)gy, 0), NH-1);

    int base = ((b*NA + best)*25)*HW + gj*NW + gi;
    float px = fsig(out[base])        + (float)gi;
    float py = fsig(out[base + HW])   + (float)gj;
    float pw = __expf(out[base + 2*HW]) * c_aw[best];
    float ph = __expf(out[base + 3*HW]) * c_ah[best];
    float uw = fmaxf(gx+0.5f*gw, px+0.5f*pw) - fminf(gx-0.5f*gw, px-0.5f*pw);
    float uh = fmaxf(gy+0.5f*gh, py+0.5f*ph) - fminf(gy-0.5f*gh, py-0.5f*ph);
    float cw = gw+pw-uw, ch = gh+ph-uh;
    float inter = (cw <= 0.f || ch <= 0.f) ? 0.f : cw*ch;
    float ig = __fdividef(inter, gw*gh + pw*ph - inter);

    s_A[tid] = make_float4(gx - (float)gi, gy - (float)gj,
                           __logf(__fdividef(gw, c_aw[best])),
                           __logf(__fdividef(gh, c_ah[best])));
    s_B[tid] = make_float2(ig, gcls);

    // candidates: iou>0.6 => |gy-(row+0.5)| < 0.5 + 0.4*gh; 2-row band center j0+1
    if (valid && fabsf(gy - ((float)j0 + 1.0f)) <= 1.0f + 0.4001f*gh + 1e-3f){
      int u = atomicAdd(&s_nc, 1);
      s_cb[u]  = make_float4(gx-0.5f*gw, gx+0.5f*gw, gy-0.5f*gh, gy+0.5f*gh);
      s_ccg[u] = 0.375f*gw*gh;
    }
    if (valid && (gj == j0 || gj == j0+1)){
      int u = atomicAdd(&s_na, 1);
      s_akey[u] = (best*NH + gj)*NW + gi;
      s_at[u]   = tid;
    }
  }
  __syncthreads();

  // ---- assignment lookup first (keys die early, lowers reg pressure) ----
  int tb0 = -1, tb1 = -1;
  {
    const int key0 = (a0*NH + jj0)*NW + i0;
    const int key1 = (a1*NH + jj1)*NW + i1;
    const int na = s_na;
    for (int u = 0; u < na; ++u){
      int k = s_akey[u], tt = s_at[u];
      if (k == key0 && tt > tb0) tb0 = tt;
      if (k == key1 && tt > tb1) tb1 = tt;
    }
  }

  // ---- Phase B: two cells per thread, fused candidate loop ----
  float x0 = fsig(p00), y0 = fsig(p01), cf0 = fsig(p04);
  float x1 = fsig(p10), y1 = fsig(p11), cf1 = fsig(p14);
  float pw0 = __expf(p02)*c_aw[a0], ph0 = __expf(p03)*c_ah[a0];
  float pw1 = __expf(p12)*c_aw[a1], ph1 = __expf(p13)*c_ah[a1];
  float px0 = x0 + (float)i0, py0 = y0 + (float)jj0;
  float px1 = x1 + (float)i1, py1 = y1 + (float)jj1;
  float xl0 = px0-0.5f*pw0, xh0 = px0+0.5f*pw0, yl0 = py0-0.5f*ph0, yh0 = py0+0.5f*ph0;
  float xl1 = px1-0.5f*pw1, xh1 = px1+0.5f*pw1, yl1 = py1-0.5f*ph1, yh1 = py1+0.5f*ph1;
  float cp0 = 0.375f*pw0*ph0, cp1 = 0.375f*pw1*ph1;

  int ov0 = 0, ov1 = 0;
  const int n = s_nc;
  for (int t = 0; t < n; ++t){
    float4 qq = s_cb[t];
    float  cg = s_ccg[t];
    float cw0 = fminf(xh0, qq.y) - fmaxf(xl0, qq.x);
    float chh0= fminf(yh0, qq.w) - fmaxf(yl0, qq.z);
    ov0 |= (fmaxf(cw0,0.f)*fmaxf(chh0,0.f) > cp0 + cg);
    float cw1 = fminf(xh1, qq.y) - fmaxf(xl1, qq.x);
    float chh1= fminf(yh1, qq.w) - fmaxf(yl1, qq.z);
    ov1 |= (fmaxf(cw1,0.f)*fmaxf(chh1,0.f) > cp1 + cg);
  }

  float lsum = 0.0f;
  {
    float tx=0.5f, ty=0.5f, tw=0.f, th=0.f, tcf=0.f;
    float cs = ov0 ? 0.f : 1.f;
    if (tb0 >= 0){
      float4 A = s_A[tb0]; float2 B = s_B[tb0];
      tx=A.x; ty=A.y; tw=A.z; th=A.w; tcf=B.x; cs=5.0f;
      int label = (int)B.y;
      float se=0.f, lsel=0.f;
      #pragma unroll
      for (int cc = 0; cc < NC; ++cc){
        float l = out[base0 + (5+cc)*HW];
        se += __expf(l);
        lsel = (cc == label) ? l : lsel;
      }
      lsum += __logf(se) - lsel;
    }
    float dx=x0-tx, dy=y0-ty, dw=p02-tw, dh=p03-th, dc=cf0-tcf;
    lsum += 0.5f*(dx*dx + dy*dy + dw*dw + dh*dh) + 0.5f*cs*dc*dc;
  }
  if (has1){
    float tx=0.5f, ty=0.5f, tw=0.f, th=0.f, tcf=0.f;
    float cs = ov1 ? 0.f : 1.f;
    if (tb1 >= 0){
      float4 A = s_A[tb1]; float2 B = s_B[tb1];
      tx=A.x; ty=A.y; tw=A.z; th=A.w; tcf=B.x; cs=5.0f;
      int label = (int)B.y;
      float se=0.f, lsel=0.f;
      #pragma unroll
      for (int cc = 0; cc < NC; ++cc){
        float l = out[base1 + (5+cc)*HW];
        se += __expf(l);
        lsel = (cc == label) ? l : lsel;
      }
      lsum += __logf(se) - lsel;
    }
    float dx=x1-tx, dy=y1-ty, dw=p12-tw, dh=p13-th, dc=cf1-tcf;
    lsum += 0.5f*(dx*dx + dy*dy + dw*dw + dh*dh) + 0.5f*cs*dc*dc;
  }

  // ---- reduce + finalize ----
  #pragma unroll
  for (int off = 16; off > 0; off >>= 1)
    lsum += __shfl_down_sync(0xffffffffu, lsum, off);
  if (lane == 0) s_ws[tid >> 5] = lsum;
  __syncthreads();

  if (tid == 0){
    float bs = 0.f;
    #pragma unroll
    for (int wv = 0; wv < TPB/32; ++wv) bs += s_ws[wv];
    atomicAdd(&g_part[blockIdx.x], (double)bs);
    __threadfence();
    unsigned long long v = atomicAdd(&g_ctr, 1ull);
    s_islast = ((v % (unsigned long long)NBLK) == (unsigned long long)(NBLK-1)) ? 1 : 0;
  }
  __syncthreads();

  if (s_islast && tid == 0){
    __threadfence();
    double tot = 0.0;
    for (int q = 0; q < GX; ++q){
      unsigned long long old = atomicExch((unsigned long long*)&g_part[q], 0ull);
      tot += __longlong_as_double((long long)old);
    }
    res[0] = (float)tot;
  }
}

extern "C" void kernel_launch(void* const* d_in, const int* in_sizes, int n_in,
                              void* d_out, int out_size){
  const float* outp = (const float*)d_in[0];
  const float* tgtp = (const float*)d_in[1];
  if (n_in >= 2 && in_sizes[0] < in_sizes[1]){
    const float* tmp = outp; outp = tgtp; tgtp = tmp;
  }
  region_kernel<<<dim3(GX, NB), TPB>>>(outp, tgtp, (float*)d_out);
}

// round 7
// speedup vs baseline: 1.1099x; 1.1099x over previous
#include <cuda_runtime.h>
#include <math_constants.h>

#define NB 64
#define NA 5
#define NC 20
#define NH 38
#define NW 38
#define HW (NH*NW)            // 1444
#define MAXB 50
#define RPB 2
#define GX (NH/RPB)           // 19
#define TPB 192
#define NACT (NA*NW)          // 190 active threads, 2 cells each (rows j0, j0+1)
#define NBLK (GX*NB)          // 1216

__constant__ float c_aw[5] = {1.3221f, 3.19275f, 5.05587f, 9.47112f, 11.2364f};
__constant__ float c_ah[5] = {1.73145f, 4.00944f, 8.09892f, 4.84053f, 10.0071f};

__device__ double             g_part[GX];
__device__ unsigned long long g_ctr;     // monotone across replays, never reset

__device__ __forceinline__ float fsig(float v){     // MUFU.TANH-based sigmoid
  return fmaf(__tanhf(0.5f*v), 0.5f, 0.5f);
}

// ---------------------------------------------------------------------------
// One fused kernel. Block = (batch b, rows j0, j0+1). 192 thr (190 active),
// 2 cells/thread sharing (anchor a, col i). Phase A is pure-ALU (no LDG/MUFU):
// the expensive per-box values (iou_gt, tw, th) are computed lazily by the
// assigned cell itself in Phase B, which already owns the identical pred box.
// ---------------------------------------------------------------------------
__global__ void __launch_bounds__(TPB) region_kernel(const float* __restrict__ out,
                                                     const float* __restrict__ tgt,
                                                     float* __restrict__ res){
  const int b   = blockIdx.y;
  const int j0  = blockIdx.x * RPB;
  const int tid = threadIdx.x;
  const int lane = tid & 31;

  __shared__ float4 s_cb[MAXB];     // candidates (xlo,xhi,ylo,yhi)
  __shared__ float  s_ccg[MAXB];    // 0.375*areaG
  __shared__ int    s_akey[MAXB];   // assignment: cell key
  __shared__ int    s_at[MAXB];     // assignment: box index t (for max-t tie-break)
  __shared__ float4 s_aA[MAXB];     // assignment payload: txv, tyv, gw, gh
  __shared__ float4 s_aB[MAXB];     // assignment payload: gxl, gxh, gyl, gyh
  __shared__ float  s_acl[MAXB];    // assignment payload: gcls
  __shared__ int    s_nc, s_na, s_w0all, s_islast;
  __shared__ float  s_ws[TPB/32];

  if (tid == 0){ s_nc = 0; s_na = 0; }

  // ---- tgt load + ballot prefix-AND validity (warps 0-1) ----
  float gcls=0.f, gx=0.f, gy=0.f, gw=0.f, gh=0.f, xn=1.0f;
  if (tid < MAXB){
    const float* p = tgt + b*(MAXB*5) + tid*5;
    gcls = p[0]; xn = p[1];
    gx = xn*(float)NW; gy = p[2]*(float)NH; gw = p[3]*(float)NW; gh = p[4]*(float)NH;
  }
  unsigned msk  = __ballot_sync(0xffffffffu, xn != 0.0f);
  unsigned need = 0xffffffffu >> (31 - lane);
  int      pre  = ((msk & need) == need);
  if (tid == 0) s_w0all = (msk == 0xffffffffu);

  // ---- cell indices (one div/mod; two cells differ only by row) ----
  const int ct = (tid < NACT) ? tid : (NACT-1);   // lanes 190,191 duplicate; masked later
  const int a0 = ct / NW, i0 = ct - a0*NW;
  const int base0 = ((b*NA + a0)*25)*HW + j0*NW + i0;   // row j0
  const int base1 = base0 + NW;                         // row j0+1

  // ---- prefetch 10 LDGs before the barrier ----
  float p00 = out[base0],        p10 = out[base1];
  float p01 = out[base0 +   HW], p11 = out[base1 +   HW];
  float p02 = out[base0 + 2*HW], p12 = out[base1 + 2*HW];
  float p03 = out[base0 + 3*HW], p13 = out[base1 + 3*HW];
  float p04 = out[base0 + 4*HW], p14 = out[base1 + 4*HW];

  __syncthreads();

  // ---- Phase A: pure-ALU per-GT-box prep (warps 0-1, no LDG/MUFU) ----
  if (tid < MAXB){
    int valid = (tid < 32) ? pre : (pre & s_w0all);

    int best = 0; float bi = -1.0f, bu = 1.0f;
    #pragma unroll
    for (int a = 0; a < NA; ++a){
      float inter = fminf(gw, c_aw[a]) * fminf(gh, c_ah[a]);
      float uni   = gw*gh + c_aw[a]*c_ah[a] - inter;
      if (inter*bu > bi*uni){ bi = inter; bu = uni; best = a; }
    }

    int gi = min(max((int)gx, 0), NW-1);
    int gj = min(max((int)gy, 0), NH-1);

    // candidates: iou>0.6 => |gy-(row+0.5)| < 0.5 + 0.4*gh; 2-row band center j0+1
    if (valid && fabsf(gy - ((float)j0 + 1.0f)) <= 1.0f + 0.4001f*gh + 1e-3f){
      int u = atomicAdd(&s_nc, 1);
      s_cb[u]  = make_float4(gx-0.5f*gw, gx+0.5f*gw, gy-0.5f*gh, gy+0.5f*gh);
      s_ccg[u] = 0.375f*gw*gh;
    }
    if (valid && (gj == j0 || gj == j0+1)){
      int u = atomicAdd(&s_na, 1);
      s_akey[u] = (best*NH + gj)*NW + gi;
      s_at[u]   = tid;
      s_aA[u]   = make_float4(gx - (float)gi, gy - (float)gj, gw, gh);
      s_aB[u]   = make_float4(gx-0.5f*gw, gx+0.5f*gw, gy-0.5f*gh, gy+0.5f*gh);
      s_acl[u]  = gcls;
    }
  }
  __syncthreads();

  // ---- assignment lookup (max-t wins = last-valid-wins) ----
  int u0 = -1, u1 = -1, tb0 = -1, tb1 = -1;
  {
    const int key0 = (a0*NH + j0)*NW + i0;
    const int key1 = key0 + NW;
    const int na = s_na;
    for (int u = 0; u < na; ++u){
      int k = s_akey[u], tt = s_at[u];
      if (k == key0 && tt > tb0){ tb0 = tt; u0 = u; }
      if (k == key1 && tt > tb1){ tb1 = tt; u1 = u; }
    }
  }

  // ---- Phase B: two cells per thread ----
  float x0 = fsig(p00), y0 = fsig(p01), cf0 = fsig(p04);
  float x1 = fsig(p10), y1 = fsig(p11), cf1 = fsig(p14);
  float pw0 = __expf(p02)*c_aw[a0], ph0 = __expf(p03)*c_ah[a0];
  float pw1 = __expf(p12)*c_aw[a0], ph1 = __expf(p13)*c_ah[a0];
  float px0 = x0 + (float)i0, py0 = y0 + (float)j0;
  float px1 = x1 + (float)i0, py1 = y1 + (float)(j0+1);
  float xl0 = px0-0.5f*pw0, xh0 = px0+0.5f*pw0, yl0 = py0-0.5f*ph0, yh0 = py0+0.5f*ph0;
  float xl1 = px1-0.5f*pw1, xh1 = px1+0.5f*pw1, yl1 = py1-0.5f*ph1, yh1 = py1+0.5f*ph1;
  float cp0 = 0.375f*pw0*ph0, cp1 = 0.375f*pw1*ph1;

  int ov0 = 0, ov1 = 0;
  const int n = s_nc;
  for (int t = 0; t < n; ++t){
    float4 qq = s_cb[t];
    float  cg = s_ccg[t];
    float cw0 = fminf(xh0, qq.y) - fmaxf(xl0, qq.x);
    float chh0= fminf(yh0, qq.w) - fmaxf(yl0, qq.z);
    ov0 |= (fmaxf(cw0,0.f)*fmaxf(chh0,0.f) > cp0 + cg);
    float cw1 = fminf(xh1, qq.y) - fmaxf(xl1, qq.x);
    float chh1= fminf(yh1, qq.w) - fmaxf(yl1, qq.z);
    ov1 |= (fmaxf(cw1,0.f)*fmaxf(chh1,0.f) > cp1 + cg);
  }

  float lsum = 0.0f;
  {
    float tx=0.5f, ty=0.5f, tw=0.f, th=0.f, tcf=0.f;
    float cs = ov0 ? 0.f : 1.f;
    if (u0 >= 0){
      float4 A = s_aA[u0]; float4 B = s_aB[u0];
      tx=A.x; ty=A.y;
      tw = __logf(__fdividef(A.z, c_aw[a0]));
      th = __logf(__fdividef(A.w, c_ah[a0]));
      // iou_gt with own pred box (identical to reference's pred_at)
      float uw = fmaxf(xh0, B.y) - fminf(xl0, B.x);
      float uh = fmaxf(yh0, B.w) - fminf(yl0, B.z);
      float cw = pw0 + A.z - uw, ch = ph0 + A.w - uh;
      float inter = (cw <= 0.f || ch <= 0.f) ? 0.f : cw*ch;
      tcf = __fdividef(inter, pw0*ph0 + A.z*A.w - inter);
      cs = 5.0f;
      int label = (int)s_acl[u0];
      float se=0.f, lsel=0.f;
      #pragma unroll
      for (int cc = 0; cc < NC; ++cc){
        float l = out[base0 + (5+cc)*HW];
        se += __expf(l);
        lsel = (cc == label) ? l : lsel;
      }
      lsum += __logf(se) - lsel;
    }
    float dx=x0-tx, dy=y0-ty, dw=p02-tw, dh=p03-th, dc=cf0-tcf;
    lsum += 0.5f*(dx*dx + dy*dy + dw*dw + dh*dh) + 0.5f*cs*dc*dc;
  }
  {
    float tx=0.5f, ty=0.5f, tw=0.f, th=0.f, tcf=0.f;
    float cs = ov1 ? 0.f : 1.f;
    if (u1 >= 0){
      float4 A = s_aA[u1]; float4 B = s_aB[u1];
      tx=A.x; ty=A.y;
      tw = __logf(__fdividef(A.z, c_aw[a0]));
      th = __logf(__fdividef(A.w, c_ah[a0]));
      float uw = fmaxf(xh1, B.y) - fminf(xl1, B.x);
      float uh = fmaxf(yh1, B.w) - fminf(yl1, B.z);
      float cw = pw1 + A.z - uw, ch = ph1 + A.w - uh;
      float inter = (cw <= 0.f || ch <= 0.f) ? 0.f : cw*ch;
      tcf = __fdividef(inter, pw1*ph1 + A.z*A.w - inter);
      cs = 5.0f;
      int label = (int)s_acl[u1];
      float se=0.f, lsel=0.f;
      #pragma unroll
      for (int cc = 0; cc < NC; ++cc){
        float l = out[base1 + (5+cc)*HW];
        se += __expf(l);
        lsel = (cc == label) ? l : lsel;
      }
      lsum += __logf(se) - lsel;
    }
    float dx=x1-tx, dy=y1-ty, dw=p12-tw, dh=p13-th, dc=cf1-tcf;
    lsum += 0.5f*(dx*dx + dy*dy + dw*dw + dh*dh) + 0.5f*cs*dc*dc;
  }

  if (tid >= NACT) lsum = 0.0f;    // duplicate lanes contribute nothing

  // ---- reduce + finalize ----
  #pragma unroll
  for (int off = 16; off > 0; off >>= 1)
    lsum += __shfl_down_sync(0xffffffffu, lsum, off);
  if (lane == 0) s_ws[tid >> 5] = lsum;
  __syncthreads();

  if (tid == 0){
    float bs = 0.f;
    #pragma unroll
    for (int wv = 0; wv < TPB/32; ++wv) bs += s_ws[wv];
    atomicAdd(&g_part[blockIdx.x], (double)bs);
    __threadfence();
    unsigned long long v = atomicAdd(&g_ctr, 1ull);
    s_islast = ((v % (unsigned long long)NBLK) == (unsigned long long)(NBLK-1)) ? 1 : 0;
  }
  __syncthreads();

  if (s_islast && tid == 0){
    __threadfence();
    double tot = 0.0;
    for (int q = 0; q < GX; ++q){
      unsigned long long old = atomicExch((unsigned long long*)&g_part[q], 0ull);
      tot += __longlong_as_double((long long)old);
    }
    res[0] = (float)tot;
  }
}

extern "C" void kernel_launch(void* const* d_in, const int* in_sizes, int n_in,
                              void* d_out, int out_size){
  const float* outp = (const float*)d_in[0];
  const float* tgtp = (const float*)d_in[1];
  if (n_in >= 2 && in_sizes[0] < in_sizes[1]){
    const float* tmp = outp; outp = tgtp; tgtp = tmp;
  }
  region_kernel<<<dim3(GX, NB), TPB>>>(outp, tgtp, (float*)d_out);
}